// round 1
// baseline (speedup 1.0000x reference)
#include <cuda_runtime.h>
#include <math.h>

#define N_ENT 100000
#define N_REL 500
#define NT    250000
#define NROWS (2*NT)
#define DIM   128
#define DIN3  384
#define BN_EPS 1e-5f
#define SLOPE 0.01f
#define REL_COPIES 32

// ---------------- static device scratch (no allocations allowed) ----------------
__device__ __align__(16) float g_PE[(size_t)N_ENT * 256];              // 102.4 MB: [P0 | P1] per entity
__device__ __align__(16) float g_Pr[N_REL * DIM];                      // 256 KB
__device__ __align__(16) float g_cpre[(size_t)NROWS * DIM];            // 256 MB fp32 scratch
__device__ __align__(16) float g_hs[(size_t)N_ENT * DIM];              // 51.2 MB
__device__ __align__(16) float g_ebs[N_ENT];
__device__            int   g_cnt_ent[N_ENT];
__device__            int   g_cnt_rel[N_REL];
__device__ __align__(16) float g_rel_sum[(size_t)REL_COPIES * N_REL * DIM]; // 8.2 MB
__device__ __align__(16) float g_sum_ent[DIM];
__device__ __align__(16) float g_sumsq_ent[DIM];
__device__ __align__(16) float g_sumsq_rel[DIM];
__device__ __align__(16) float g_s0[DIN3];
__device__ __align__(16) float g_moff[DIN3];
__device__ __align__(16) float g_WtE[128 * 256];                       // k-major, j in [0,256)
__device__ __align__(16) float g_WtR[128 * 128];                       // k-major
__device__ __align__(16) float g_biasp[DIM];
__device__ __align__(16) float g_sum1[DIM];
__device__ __align__(16) float g_sumsq1[DIM];
__device__ __align__(16) float g_s1[DIM];
__device__ __align__(16) float g_b1p[DIM];

// ---------------- small helpers ----------------
__device__ __forceinline__ void red_add_v4(float* a, float4 v) {
    asm volatile("red.global.add.v4.f32 [%0], {%1,%2,%3,%4};"
                 :: "l"(a), "f"(v.x), "f"(v.y), "f"(v.z), "f"(v.w) : "memory");
}

// ---------------- K0: zero all accumulators (graph replays!) ----------------
__global__ void k_zero() {
    size_t i = (size_t)blockIdx.x * blockDim.x + threadIdx.x;
    size_t stride = (size_t)gridDim.x * blockDim.x;
    for (size_t x = i; x < (size_t)N_ENT * DIM; x += stride) g_hs[x] = 0.f;
    for (size_t x = i; x < (size_t)REL_COPIES * N_REL * DIM; x += stride) g_rel_sum[x] = 0.f;
    for (size_t x = i; x < N_ENT; x += stride) { g_ebs[x] = 0.f; g_cnt_ent[x] = 0; }
    if (i < N_REL) g_cnt_rel[i] = 0;
    if (i < DIM) {
        g_sum_ent[i] = 0.f; g_sumsq_ent[i] = 0.f; g_sumsq_rel[i] = 0.f;
        g_sum1[i] = 0.f; g_sumsq1[i] = 0.f;
    }
}

// ---------------- K1: bincount entities (t0 U t1) and relations ----------------
__global__ void k_count(const int* __restrict__ trip) {
    int i = blockIdx.x * blockDim.x + threadIdx.x;
    if (i < NT) {
        atomicAdd(&g_cnt_ent[trip[3 * i + 0]], 1);
        atomicAdd(&g_cnt_ent[trip[3 * i + 1]], 1);
        atomicAdd(&g_cnt_rel[trip[3 * i + 2]], 1);
    }
}

// ---------------- K2: count-weighted bn0 stats over entity table ----------------
__global__ void k_ent_stats(const float* __restrict__ ent) {
    int t = threadIdx.x; int k = t & 127; int eh = t >> 7;
    float s = 0.f, q = 0.f;
    for (int e = blockIdx.x * 2 + eh; e < N_ENT; e += gridDim.x * 2) {
        float w = (float)g_cnt_ent[e];
        float x = ent[(size_t)e * DIM + k];
        s += w * x; q += w * x * x;
    }
    __shared__ float ss[256], sq[256];
    ss[t] = s; sq[t] = q; __syncthreads();
    if (t < 128) {
        atomicAdd(&g_sum_ent[k],   ss[t] + ss[t + 128]);
        atomicAdd(&g_sumsq_ent[k], sq[t] + sq[t + 128]);
    }
}

__global__ void k_rel_stats(const float* __restrict__ relw) {
    int t = threadIdx.x; int k = t & 127; int rh = t >> 7;
    float q = 0.f;
    for (int r = blockIdx.x * 2 + rh; r < N_REL; r += gridDim.x * 2) {
        float w = (float)g_cnt_rel[r];
        float x = relw[r * DIM + k];
        q += w * x * x;
    }
    __shared__ float sq[256];
    sq[t] = q; __syncthreads();
    if (t < 128) atomicAdd(&g_sumsq_rel[k], sq[t] + sq[t + 128]);
}

// ---------------- K3: fold bn0 into the projection weights ----------------
__global__ void k_fold_s0(const float* __restrict__ bn0g, const float* __restrict__ bn0b) {
    int k = threadIdx.x; // 0..383
    float mean, var;
    if (k < 256) {
        mean = g_sum_ent[k & 127] / (float)NROWS;
        var  = g_sumsq_ent[k & 127] / (float)NROWS - mean * mean;
    } else {
        mean = 0.f;
        var  = g_sumsq_rel[k - 256] / (float)NT; // concat(r,-r): E=0, var = E[r^2]
    }
    float s = bn0g[k] * rsqrtf(var + BN_EPS);
    g_s0[k] = s;
    g_moff[k] = bn0b[k] - mean * s;
}

__global__ void k_build_w(const float* __restrict__ a_w) {
    int idx = blockIdx.x * blockDim.x + threadIdx.x;
    if (idx >= DIN3 * 128) return;
    int kk = idx / 128;   // column of a_w (0..383)
    int j  = idx % 128;   // output row
    float v = a_w[j * DIN3 + kk] * g_s0[kk];
    if (kk < 128)       g_WtE[kk * 256 + j]               = v;
    else if (kk < 256)  g_WtE[(kk - 128) * 256 + 128 + j] = v;
    else                g_WtR[(kk - 256) * 128 + j]       = v;
}

__global__ void k_bias(const float* __restrict__ a_w, const float* __restrict__ a_b) {
    int j = threadIdx.x;
    float acc = 0.f;
    for (int k = 0; k < DIN3; k++) acc += g_moff[k] * a_w[j * DIN3 + k];
    g_biasp[j] = a_b[j] + acc;
}

// ---------------- K4: PE[e][0:256] = ent[e] @ [W0'|W1']^T  (fp32x2 FMA) --------
__global__ void __launch_bounds__(512, 1) k_gemm_pe(const float* __restrict__ ent) {
    extern __shared__ float smem[];
    float* sW   = smem;                 // 128*256 floats (k-major)
    float* sRow = smem + 128 * 256;     // 16 warps * 8 rows * 128
    for (int i = threadIdx.x; i < (128 * 256) / 4; i += blockDim.x)
        ((float4*)sW)[i] = ((const float4*)g_WtE)[i];
    __syncthreads();

    int lane  = threadIdx.x & 31;
    int wid   = threadIdx.x >> 5;
    int gwarp = blockIdx.x * 16 + wid;
    int nwarps = gridDim.x * 16;
    float* rbuf = sRow + wid * 8 * 128;
    const float4* ent4 = (const float4*)ent;
    const int jb = lane * 8;

    for (int base = gwarp * 8; base < N_ENT; base += nwarps * 8) {
        #pragma unroll
        for (int r = 0; r < 8; r++) {
            int row = base + r; if (row >= N_ENT) row = base;
            ((float4*)rbuf)[r * 32 + lane] = ent4[(size_t)row * 32 + lane];
        }
        __syncwarp();

        unsigned long long acc[8][4];
        #pragma unroll
        for (int r = 0; r < 8; r++)
            #pragma unroll
            for (int p = 0; p < 4; p++) acc[r][p] = 0ull;

        #pragma unroll 4
        for (int k = 0; k < 128; k++) {
            ulonglong2 wA = *(const ulonglong2*)&sW[k * 256 + jb];
            ulonglong2 wB = *(const ulonglong2*)&sW[k * 256 + jb + 4];
            #pragma unroll
            for (int r = 0; r < 8; r++) {
                float x = rbuf[r * 128 + k];          // LDS broadcast
                unsigned long long xb;
                asm("mov.b64 %0, {%1, %1};" : "=l"(xb) : "f"(x));
                asm("fma.rn.f32x2 %0, %1, %2, %0;" : "+l"(acc[r][0]) : "l"(xb), "l"(wA.x));
                asm("fma.rn.f32x2 %0, %1, %2, %0;" : "+l"(acc[r][1]) : "l"(xb), "l"(wA.y));
                asm("fma.rn.f32x2 %0, %1, %2, %0;" : "+l"(acc[r][2]) : "l"(xb), "l"(wB.x));
                asm("fma.rn.f32x2 %0, %1, %2, %0;" : "+l"(acc[r][3]) : "l"(xb), "l"(wB.y));
            }
        }

        #pragma unroll
        for (int r = 0; r < 8; r++) {
            int row = base + r;
            if (row < N_ENT) {
                float o[8];
                #pragma unroll
                for (int p = 0; p < 4; p++)
                    asm("mov.b64 {%0, %1}, %2;" : "=f"(o[2*p]), "=f"(o[2*p+1]) : "l"(acc[r][p]));
                float4* dst = (float4*)&g_PE[(size_t)row * 256 + jb];
                dst[0] = make_float4(o[0], o[1], o[2], o[3]);
                dst[1] = make_float4(o[4], o[5], o[6], o[7]);
            }
        }
        __syncwarp();
    }
}

// ---------------- K4b: Pr[r] = rel[r] @ W2'^T ----------------
__global__ void k_gemm_pr(const float* __restrict__ relw) {
    __shared__ float srow[128];
    int r = blockIdx.x; int j = threadIdx.x;
    srow[j] = relw[r * DIM + j];
    __syncthreads();
    float acc = 0.f;
    #pragma unroll 4
    for (int k = 0; k < 128; k++) acc += srow[k] * g_WtR[k * 128 + j];
    g_Pr[r * DIM + j] = acc;
}

// ---------------- K6 (pass A): assemble c_pre rows + bn1 column sums ----------
__global__ void k_passA(const int* __restrict__ trip) {
    __shared__ float ssum[128], sssq[128];
    int t = threadIdx.x;
    if (t < 128) { ssum[t] = 0.f; sssq[t] = 0.f; }
    __syncthreads();
    int lane = t & 31, wid = t >> 5;
    int gwarp = blockIdx.x * 8 + wid;
    int nwarps = gridDim.x * 8;
    float4 ls = make_float4(0, 0, 0, 0), lq = make_float4(0, 0, 0, 0);
    const float4 bias = ((const float4*)g_biasp)[lane];

    for (int i = gwarp; i < NT; i += nwarps) {
        int t0 = trip[3 * i], t1 = trip[3 * i + 1], t2 = trip[3 * i + 2];
        const float4* p0 = (const float4*)&g_PE[(size_t)t0 * 256];
        const float4* p1 = (const float4*)&g_PE[(size_t)t1 * 256];
        float4 a0 = p0[lane],      b0 = p0[32 + lane];
        float4 a1 = p1[lane],      b1 = p1[32 + lane];
        float4 pr = ((const float4*)&g_Pr[t2 * DIM])[lane];
        float4 cf, cb;
        cf.x = a0.x + b1.x + pr.x + bias.x;  cb.x = a1.x + b0.x - pr.x + bias.x;
        cf.y = a0.y + b1.y + pr.y + bias.y;  cb.y = a1.y + b0.y - pr.y + bias.y;
        cf.z = a0.z + b1.z + pr.z + bias.z;  cb.z = a1.z + b0.z - pr.z + bias.z;
        cf.w = a0.w + b1.w + pr.w + bias.w;  cb.w = a1.w + b0.w - pr.w + bias.w;
        ((float4*)&g_cpre[(size_t)i * DIM])[lane] = cf;
        ((float4*)&g_cpre[(size_t)(NT + i) * DIM])[lane] = cb;
        ls.x += cf.x + cb.x;  lq.x += cf.x * cf.x + cb.x * cb.x;
        ls.y += cf.y + cb.y;  lq.y += cf.y * cf.y + cb.y * cb.y;
        ls.z += cf.z + cb.z;  lq.z += cf.z * cf.z + cb.z * cb.z;
        ls.w += cf.w + cb.w;  lq.w += cf.w * cf.w + cb.w * cb.w;
    }
    atomicAdd(&ssum[4 * lane + 0], ls.x); atomicAdd(&sssq[4 * lane + 0], lq.x);
    atomicAdd(&ssum[4 * lane + 1], ls.y); atomicAdd(&sssq[4 * lane + 1], lq.y);
    atomicAdd(&ssum[4 * lane + 2], ls.z); atomicAdd(&sssq[4 * lane + 2], lq.z);
    atomicAdd(&ssum[4 * lane + 3], ls.w); atomicAdd(&sssq[4 * lane + 3], lq.w);
    __syncthreads();
    if (t < 128) {
        atomicAdd(&g_sum1[t],   ssum[t]);
        atomicAdd(&g_sumsq1[t], sssq[t]);
    }
}

// ---------------- K5: bn1 finalize ----------------
__global__ void k_bn1(const float* __restrict__ bn1g, const float* __restrict__ bn1b) {
    int j = threadIdx.x;
    float mean = g_sum1[j] / (float)NROWS;
    float var  = g_sumsq1[j] / (float)NROWS - mean * mean;
    float s = bn1g[j] * rsqrtf(var + BN_EPS);
    g_s1[j]  = s;
    g_b1p[j] = bn1b[j] - mean * s;
}

// ---------------- K8 (pass B): attention + scatter ----------------
__global__ void k_passB(const int* __restrict__ trip,
                        const float* __restrict__ a2w, const float* __restrict__ a2b) {
    int lane = threadIdx.x & 31, wid = threadIdx.x >> 5;
    int row = blockIdx.x * 8 + wid;
    if (row >= NROWS) return;
    int i   = (row < NT) ? row : row - NT;
    int seg = (row < NT) ? trip[3 * i] : trip[3 * i + 1];

    float4 cp = ((const float4*)&g_cpre[(size_t)row * DIM])[lane];
    float4 s1 = ((const float4*)g_s1)[lane];
    float4 b1 = ((const float4*)g_b1p)[lane];
    float4 c;
    c.x = cp.x * s1.x + b1.x;
    c.y = cp.y * s1.y + b1.y;
    c.z = cp.z * s1.z + b1.z;
    c.w = cp.w * s1.w + b1.w;

    float4 w = ((const float4*)a2w)[lane];
    float d = c.x * w.x + c.y * w.y + c.z * w.z + c.w * w.w;
    #pragma unroll
    for (int o = 16; o; o >>= 1) d += __shfl_xor_sync(0xffffffffu, d, o);
    d += a2b[0];
    float lr = (d >= 0.f) ? d : SLOPE * d;
    float e = expf(-lr);

    float4 tv;
    tv.x = e * c.x; tv.y = e * c.y; tv.z = e * c.z; tv.w = e * c.w;
    red_add_v4(&g_hs[(size_t)seg * DIM + 4 * lane], tv);
    if (lane == 0) atomicAdd(&g_ebs[seg], e);
    if (row < NT) {
        int t2 = trip[3 * i + 2];
        int cpx = row & (REL_COPIES - 1);
        red_add_v4(&g_rel_sum[((size_t)cpx * N_REL + t2) * DIM + 4 * lane], tv);
    }
}

// ---------------- K9: finalize outputs ----------------
__global__ void k_out_ent(float* __restrict__ out) {
    int idx = blockIdx.x * blockDim.x + threadIdx.x;
    if (idx >= N_ENT * 32) return;
    int e = idx >> 5, q = idx & 31;
    float eb = g_ebs[e];
    float inv = 1.f / ((eb == 0.f) ? 1e-12f : eb);
    float4 h = ((const float4*)&g_hs[(size_t)e * DIM])[q];
    h.x *= inv; h.y *= inv; h.z *= inv; h.w *= inv;
    ((float4*)out)[idx] = h;
}

__global__ void k_out_rel(float* __restrict__ out) {
    int idx = blockIdx.x * blockDim.x + threadIdx.x;
    if (idx >= N_REL * 32) return;
    int r = idx >> 5, q = idx & 31;
    float4 acc = make_float4(0, 0, 0, 0);
    #pragma unroll 4
    for (int cp = 0; cp < REL_COPIES; cp++) {
        float4 v = ((const float4*)&g_rel_sum[((size_t)cp * N_REL + r) * DIM])[q];
        acc.x += v.x; acc.y += v.y; acc.z += v.z; acc.w += v.w;
    }
    float cnt = fmaxf((float)g_cnt_rel[r], 1.f);
    acc.x /= cnt; acc.y /= cnt; acc.z /= cnt; acc.w /= cnt;
    ((float4*)(out + (size_t)N_ENT * DIM))[idx] = acc;
}

// ---------------- launch ----------------
extern "C" void kernel_launch(void* const* d_in, const int* in_sizes, int n_in,
                              void* d_out, int out_size) {
    const int*   trip = (const int*)d_in[0];
    const float* ent  = (const float*)d_in[1];
    const float* relw = (const float*)d_in[2];
    const float* a_w  = (const float*)d_in[3];
    const float* a_b  = (const float*)d_in[4];
    const float* a2w  = (const float*)d_in[5];
    const float* a2b  = (const float*)d_in[6];
    const float* bn0g = (const float*)d_in[7];
    const float* bn0b = (const float*)d_in[8];
    const float* bn1g = (const float*)d_in[9];
    const float* bn1b = (const float*)d_in[10];
    float* out = (float*)d_out;

    const int smem_k4 = (128 * 256 + 16 * 8 * 128) * (int)sizeof(float); // 192 KB
    cudaFuncSetAttribute(k_gemm_pe, cudaFuncAttributeMaxDynamicSharedMemorySize, smem_k4);

    k_zero<<<2048, 256>>>();
    k_count<<<(NT + 255) / 256, 256>>>(trip);
    k_ent_stats<<<256, 256>>>(ent);
    k_rel_stats<<<8, 256>>>(relw);
    k_fold_s0<<<1, DIN3>>>(bn0g, bn0b);
    k_build_w<<<(DIN3 * 128 + 255) / 256, 256>>>(a_w);
    k_bias<<<1, 128>>>(a_w, a_b);
    k_gemm_pe<<<148, 512, smem_k4>>>(ent);
    k_gemm_pr<<<N_REL, 128>>>(relw);
    k_passA<<<592, 256>>>(trip);
    k_bn1<<<1, 128>>>(bn1g, bn1b);
    k_passB<<<(NROWS + 7) / 8, 256>>>(trip, a2w, a2b);
    k_out_ent<<<(N_ENT * 32 + 255) / 256, 256>>>(out);
    k_out_rel<<<(N_REL * 32 + 255) / 256, 256>>>(out);
}